// round 3
// baseline (speedup 1.0000x reference)
#include <cuda_runtime.h>
#include <math.h>

#define BB 4
#define SS 4096
#define NSTR 4
#define DD 1024
#define ND (NSTR * DD)            // 4096 floats per (b,s)
#define ND4 (ND / 4)              // 1024 float4 per (b,s)
#define D4 (DD / 4)               // 256 float4 per stream row
#define NCOLS 24
#define SCHUNKS 32
#define SPERCHUNK (SS / SCHUNKS)  // 128

// Scratch (allocation-free rule: __device__ globals)
__device__ float g_partial[BB][SCHUNKS][ND];   // 2 MB
__device__ float g_gates[BB][24];              // pre[4], post[4], res P[16]

// ---------------------------------------------------------------------------
// Kernel 1: partial sums of H over S. float4-vectorized.
// DEFAULT-cached loads: the trailing ~126MB of H stays resident in L2 so
// k_mix's re-read of H hits L2 instead of DRAM.
// grid: (ND4/256=4, SCHUNKS, B), block 256.
// ---------------------------------------------------------------------------
__global__ void __launch_bounds__(256) k_reduce(const float4* __restrict__ H4) {
    const int b     = blockIdx.z;
    const int chunk = blockIdx.y;
    const int col4  = blockIdx.x * 256 + threadIdx.x;  // 0..ND4-1
    const float4* base = H4 + ((size_t)b * SS + (size_t)chunk * SPERCHUNK) * ND4 + col4;
    float4 acc = make_float4(0.f, 0.f, 0.f, 0.f);
#pragma unroll 16
    for (int s = 0; s < SPERCHUNK; s++) {
        const float4 v = base[(size_t)s * ND4];   // default .ca -> stays in L2
        acc.x += v.x; acc.y += v.y; acc.z += v.z; acc.w += v.w;
    }
    ((float4*)&g_partial[b][chunk][0])[col4] = acc;
}

// ---------------------------------------------------------------------------
// Kernel 2: finish mean, RMS-normalize, delta = x @ phi, gates + Sinkhorn.
// grid: B blocks, 1024 threads
// ---------------------------------------------------------------------------
__global__ void k_gates(const float* __restrict__ phi,
                        const float* __restrict__ pre_base,
                        const float* __restrict__ post_base,
                        const float* __restrict__ res_base,
                        const float* __restrict__ a_pre,
                        const float* __restrict__ a_post,
                        const float* __restrict__ a_res) {
    const int b    = blockIdx.x;
    const int tid  = threadIdx.x;
    const int lane = tid & 31;
    const int warp = tid >> 5;

    __shared__ float swarp[32];
    __shared__ float sred[32 * NCOLS];
    __shared__ float sdelta[NCOLS];
    __shared__ float s_invrms;

    float xloc[4];
#pragma unroll
    for (int r = 0; r < 4; r++) {
        const int c = tid + r * 1024;
        float acc = 0.0f;
#pragma unroll
        for (int ch = 0; ch < SCHUNKS; ch++) acc += g_partial[b][ch][c];
        xloc[r] = acc * (1.0f / (float)SS);
    }

    float ss = xloc[0] * xloc[0] + xloc[1] * xloc[1]
             + xloc[2] * xloc[2] + xloc[3] * xloc[3];
#pragma unroll
    for (int o = 16; o > 0; o >>= 1) ss += __shfl_down_sync(0xffffffffu, ss, o);
    if (lane == 0) swarp[warp] = ss;
    __syncthreads();
    if (tid == 0) {
        float t = 0.0f;
#pragma unroll
        for (int w = 0; w < 32; w++) t += swarp[w];
        s_invrms = 1.0f / sqrtf(t * (1.0f / (float)ND) + 1e-6f);
    }
    __syncthreads();
    const float invrms = s_invrms;

    float acc24[NCOLS];
#pragma unroll
    for (int j = 0; j < NCOLS; j++) acc24[j] = 0.0f;
#pragma unroll
    for (int r = 0; r < 4; r++) {
        const int c = tid + r * 1024;
        const float xv = xloc[r] * invrms;
        const float* ph = phi + (size_t)c * NCOLS;
#pragma unroll
        for (int j = 0; j < NCOLS; j++) acc24[j] += xv * ph[j];
    }
#pragma unroll
    for (int j = 0; j < NCOLS; j++) {
#pragma unroll
        for (int o = 16; o > 0; o >>= 1)
            acc24[j] += __shfl_down_sync(0xffffffffu, acc24[j], o);
    }
    if (lane == 0) {
#pragma unroll
        for (int j = 0; j < NCOLS; j++) sred[warp * NCOLS + j] = acc24[j];
    }
    __syncthreads();
    if (tid < NCOLS) {
        float t = 0.0f;
#pragma unroll
        for (int w = 0; w < 32; w++) t += sred[w * NCOLS + tid];
        sdelta[tid] = t;
    }
    __syncthreads();

    if (tid == 0) {
        const float ap  = *a_pre;
        const float apo = *a_post;
        const float ar  = *a_res;

        float pre[4];
        float psum = 0.0f;
#pragma unroll
        for (int k = 0; k < 4; k++) {
            pre[k] = 1.0f / (1.0f + expf(-(pre_base[k] + ap * sdelta[k])));
            psum += pre[k];
        }
        const float pinv = 1.0f / (psum + 1e-8f);
#pragma unroll
        for (int k = 0; k < 4; k++) g_gates[b][k] = pre[k] * pinv;

#pragma unroll
        for (int k = 0; k < 4; k++)
            g_gates[b][4 + k] = 1.0f / (1.0f + expf(-(post_base[k] + apo * sdelta[4 + k])));

        float P[16];
#pragma unroll
        for (int t = 0; t < 16; t++)
            P[t] = expf(res_base[t] + ar * sdelta[8 + t]);
        for (int it = 0; it < 20; it++) {
#pragma unroll
            for (int i = 0; i < 4; i++) {
                const float rs = P[i * 4 + 0] + P[i * 4 + 1] + P[i * 4 + 2] + P[i * 4 + 3];
                const float inv = 1.0f / (rs + 1e-6f);
                P[i * 4 + 0] *= inv; P[i * 4 + 1] *= inv;
                P[i * 4 + 2] *= inv; P[i * 4 + 3] *= inv;
            }
#pragma unroll
            for (int j = 0; j < 4; j++) {
                const float cs = P[0 * 4 + j] + P[1 * 4 + j] + P[2 * 4 + j] + P[3 * 4 + j];
                const float inv = 1.0f / (cs + 1e-6f);
                P[0 * 4 + j] *= inv; P[1 * 4 + j] *= inv;
                P[2 * 4 + j] *= inv; P[3 * 4 + j] *= inv;
            }
        }
#pragma unroll
        for (int t = 0; t < 16; t++) g_gates[b][8 + t] = P[t];
    }
}

// ---------------------------------------------------------------------------
// Kernel 3: streaming mix. One block per TWO (b,s) rows; 256 threads.
// H loads .cs (hit L2 lines left by k_reduce, evict-first after use);
// output stores .cs (don't pollute L2).
// out layout: [B][S][5][D]; row 0 = branch_input, rows 1..4 = H_new.
// ---------------------------------------------------------------------------
__global__ void __launch_bounds__(256) k_mix(const float* __restrict__ H,
                                             const float* __restrict__ bo,
                                             float* __restrict__ out) {
    const int bs0 = blockIdx.x * 2;
    const int bs1 = bs0 + 1;
    const int b   = bs0 >> 12;          // /4096
    const int d4  = threadIdx.x;        // 0..255

    __shared__ float g[24];
    if (threadIdx.x < 24) g[threadIdx.x] = g_gates[b][threadIdx.x];

    const float4* hA = (const float4*)(H + (size_t)bs0 * ND);
    const float4* hB = (const float4*)(H + (size_t)bs1 * ND);

    const float4 a0 = __ldcs(hA + 0 * D4 + d4);
    const float4 a1 = __ldcs(hA + 1 * D4 + d4);
    const float4 a2 = __ldcs(hA + 2 * D4 + d4);
    const float4 a3 = __ldcs(hA + 3 * D4 + d4);
    const float4 av = __ldcs((const float4*)(bo + (size_t)bs0 * DD) + d4);
    const float4 b0 = __ldcs(hB + 0 * D4 + d4);
    const float4 b1 = __ldcs(hB + 1 * D4 + d4);
    const float4 b2 = __ldcs(hB + 2 * D4 + d4);
    const float4 b3 = __ldcs(hB + 3 * D4 + d4);
    const float4 bv = __ldcs((const float4*)(bo + (size_t)bs1 * DD) + d4);

    __syncthreads();

    float4* oA = (float4*)(out + (size_t)bs0 * 5 * DD);
    float4* oB = (float4*)(out + (size_t)bs1 * 5 * DD);

    {
        float4 o;
        o.x = g[0]*a0.x + g[1]*a1.x + g[2]*a2.x + g[3]*a3.x;
        o.y = g[0]*a0.y + g[1]*a1.y + g[2]*a2.y + g[3]*a3.y;
        o.z = g[0]*a0.z + g[1]*a1.z + g[2]*a2.z + g[3]*a3.z;
        o.w = g[0]*a0.w + g[1]*a1.w + g[2]*a2.w + g[3]*a3.w;
        __stcs(oA + d4, o);
        o.x = g[0]*b0.x + g[1]*b1.x + g[2]*b2.x + g[3]*b3.x;
        o.y = g[0]*b0.y + g[1]*b1.y + g[2]*b2.y + g[3]*b3.y;
        o.z = g[0]*b0.z + g[1]*b1.z + g[2]*b2.z + g[3]*b3.z;
        o.w = g[0]*b0.w + g[1]*b1.w + g[2]*b2.w + g[3]*b3.w;
        __stcs(oB + d4, o);
    }

#pragma unroll
    for (int i = 0; i < 4; i++) {
        const float r0 = g[8 + i * 4 + 0];
        const float r1 = g[8 + i * 4 + 1];
        const float r2 = g[8 + i * 4 + 2];
        const float r3 = g[8 + i * 4 + 3];
        const float p  = g[4 + i];
        float4 o;
        o.x = r0*a0.x + r1*a1.x + r2*a2.x + r3*a3.x + p*av.x;
        o.y = r0*a0.y + r1*a1.y + r2*a2.y + r3*a3.y + p*av.y;
        o.z = r0*a0.z + r1*a1.z + r2*a2.z + r3*a3.z + p*av.z;
        o.w = r0*a0.w + r1*a1.w + r2*a2.w + r3*a3.w + p*av.w;
        __stcs(oA + (1 + i) * D4 + d4, o);
        o.x = r0*b0.x + r1*b1.x + r2*b2.x + r3*b3.x + p*bv.x;
        o.y = r0*b0.y + r1*b1.y + r2*b2.y + r3*b3.y + p*bv.y;
        o.z = r0*b0.z + r1*b1.z + r2*b2.z + r3*b3.z + p*bv.z;
        o.w = r0*b0.w + r1*b1.w + r2*b2.w + r3*b3.w + p*bv.w;
        __stcs(oB + (1 + i) * D4 + d4, o);
    }
}

// ---------------------------------------------------------------------------
extern "C" void kernel_launch(void* const* d_in, const int* in_sizes, int n_in,
                              void* d_out, int out_size) {
    const float* H         = (const float*)d_in[0];
    const float* branch_o  = (const float*)d_in[1];
    const float* phi       = (const float*)d_in[2];
    const float* pre_base  = (const float*)d_in[3];
    const float* post_base = (const float*)d_in[4];
    const float* res_base  = (const float*)d_in[5];
    const float* a_pre     = (const float*)d_in[6];
    const float* a_post    = (const float*)d_in[7];
    const float* a_res     = (const float*)d_in[8];
    float* out = (float*)d_out;

    dim3 g1(ND4 / 256, SCHUNKS, BB);
    k_reduce<<<g1, 256>>>((const float4*)H);
    k_gates<<<BB, 1024>>>(phi, pre_base, post_base, res_base, a_pre, a_post, a_res);
    k_mix<<<BB * SS / 2, 256>>>(H, branch_o, out);
}